// round 6
// baseline (speedup 1.0000x reference)
#include <cuda_runtime.h>
#include <cuda_fp16.h>
#include <math.h>

// ---------------------------------------------------------------------------
// MolecularGNN: 3x GCNConv(+BN+ReLU) -> global mean pool -> MLP head
// CSR src-only gather + fp16 operand + f32x2 packed-FMA GEMMs.
// ---------------------------------------------------------------------------

#define N_NODES  100000
#define N_EDGES  3200000
#define N_GRAPHS 4096
#define BN_EPS   1e-5f
#define NB_SCAN  98          // ceil(100000/1024)

// ---- scratch (device globals; allocation-free rule) -----------------------
__device__ __align__(256) int    g_ecnt  [N_NODES];
__device__ __align__(256) int    g_off   [N_NODES + 1];
__device__ __align__(256) int    g_cursor[N_NODES];
__device__ __align__(256) int    g_bsum  [NB_SCAN];
__device__ __align__(256) int    g_boff  [NB_SCAN];
__device__ __align__(256) float  g_dinv  [N_NODES];
__device__ __align__(256) int    g_csr   [N_EDGES];        // src only
__device__ __align__(256) __half g_xs    [N_NODES * 36];   // x * dinv (fp16)
__device__ __align__(256) float  g_t     [N_NODES * 36];   // aggregated x
__device__ __align__(256) __half g_xw    [N_NODES * 128];  // (h@W)*dinv (fp16)
__device__ __align__(256) float  g_bufB  [N_NODES * 128];  // h (fp32)
__device__ __align__(256) float  g_sums  [N_GRAPHS * 64];
__device__ __align__(256) float  g_cnt   [N_GRAPHS];

__device__ __forceinline__ void red_add_f32(float* p, float v) {
    asm volatile("red.global.add.f32 [%0], %1;" :: "l"(p), "f"(v) : "memory");
}
__device__ __forceinline__ unsigned long long pack2(float w) {
    unsigned long long w2;
    asm("mov.b64 %0, {%1, %1};" : "=l"(w2) : "f"(w));
    return w2;
}
__device__ __forceinline__ void fma2(unsigned long long& acc,
                                     unsigned long long a,
                                     unsigned long long b) {
    asm("fma.rn.f32x2 %0, %1, %2, %0;" : "+l"(acc) : "l"(a), "l"(b));
}
__device__ __forceinline__ float2 unpack2(unsigned long long v) {
    float lo, hi;
    asm("mov.b64 {%0, %1}, %2;" : "=f"(lo), "=f"(hi) : "l"(v));
    return make_float2(lo, hi);
}

// ---- degree count ---------------------------------------------------------
__global__ void deg_count_kernel(const int* __restrict__ dst) {
    int stride = gridDim.x * blockDim.x;
    for (int e = blockIdx.x * blockDim.x + threadIdx.x; e < N_EDGES; e += stride)
        atomicAdd(&g_ecnt[dst[e]], 1);
}

// ---- multi-block exclusive scan over g_ecnt -------------------------------
__global__ void scan_blocks_kernel() {   // NB_SCAN blocks x 1024
    __shared__ int wsum[32];
    const int t    = threadIdx.x;
    const int lane = t & 31;
    const int w    = t >> 5;
    const int i    = blockIdx.x * 1024 + t;
    int v = (i < N_NODES) ? g_ecnt[i] : 0;
    int s = v;
#pragma unroll
    for (int o = 1; o < 32; o <<= 1) {
        int u = __shfl_up_sync(0xffffffffu, s, o);
        if (lane >= o) s += u;
    }
    if (lane == 31) wsum[w] = s;
    __syncthreads();
    if (w == 0) {
        int ws = wsum[lane];
        int tt = ws;
#pragma unroll
        for (int o = 1; o < 32; o <<= 1) {
            int u = __shfl_up_sync(0xffffffffu, tt, o);
            if (lane >= o) tt += u;
        }
        wsum[lane] = tt - ws;   // exclusive warp offset
    }
    __syncthreads();
    int excl = s - v + wsum[w];
    if (i < N_NODES) g_off[i] = excl;
    if (t == 1023) g_bsum[blockIdx.x] = excl + v;   // block total
}

__global__ void scan_bsum_kernel() {     // 1 block x 128
    __shared__ int sh[128];
    const int t = threadIdx.x;
    int v = (t < NB_SCAN) ? g_bsum[t] : 0;
    sh[t] = v;
    __syncthreads();
    for (int o = 1; o < 128; o <<= 1) {
        int u = (t >= o) ? sh[t - o] : 0;
        __syncthreads();
        sh[t] += u;
        __syncthreads();
    }
    if (t < NB_SCAN) g_boff[t] = sh[t] - v;
    if (t == 127)    g_off[N_NODES] = sh[127];
}

// ---- finalize offsets + dinv + cursor -------------------------------------
__global__ void dinv_kernel() {
    int i = blockIdx.x * blockDim.x + threadIdx.x;
    if (i < N_NODES) {
        int off = g_off[i] + g_boff[i >> 10];
        g_off[i]    = off;
        g_cursor[i] = off;
        g_dinv[i]   = rsqrtf((float)g_ecnt[i] + 1.0f);
    }
}

// ---- CSR fill (src only) --------------------------------------------------
__global__ void fill_kernel(const int* __restrict__ src, const int* __restrict__ dst) {
    int stride = gridDim.x * blockDim.x;
    for (int e = blockIdx.x * blockDim.x + threadIdx.x; e < N_EDGES; e += stride) {
        int d = dst[e];
        int pos = atomicAdd(&g_cursor[d], 1);
        g_csr[pos] = src[e];
    }
}

// ---- x * dinv -> fp16 -----------------------------------------------------
__global__ void x2h_kernel(const float* __restrict__ x) {
    int i = blockIdx.x * blockDim.x + threadIdx.x;   // over N_NODES*36
    if (i < N_NODES * 36) {
        int n = i / 36;
        g_xs[i] = __float2half_rn(x[i] * g_dinv[n]);
    }
}

// ---- layer-0 aggregation over 36-wide fp16 rows ---------------------------
__global__ void agg0_kernel() {
    const int tid  = threadIdx.x;
    const int lane = tid & 31;
    const int wid  = tid >> 5;
    const int node = blockIdx.x * 8 + wid;
    if (node >= N_NODES) return;

    const int beg = g_off[node];
    const int end = g_off[node + 1];

    float a0 = 0.0f, a1 = 0.0f;
    const bool act = (lane < 18);

    auto gather = [&](int s) {
        if (act) {
            __half2 v = *reinterpret_cast<const __half2*>(g_xs + (size_t)s * 36 + lane * 2);
            float2 f = __half22float2(v);
            a0 += f.x; a1 += f.y;
        }
    };

    int b = beg;
    const int nfull = (end - beg) & ~31;
    for (; b < beg + nfull; b += 32) {
        int pk = g_csr[b + lane];
#pragma unroll 8
        for (int j = 0; j < 32; j++) {
            int s = __shfl_sync(0xffffffffu, pk, j);
            gather(s);
        }
    }
    if (b < end) {
        int e = b + lane;
        int ssrc = (e < end) ? g_csr[e] : 0;
        int cnt = end - b;
        for (int j = 0; j < cnt; j++) {
            int s = __shfl_sync(0xffffffffu, ssrc, j);
            gather(s);
        }
    }
    gather(node);   // self loop

    if (act) {
        float di = g_dinv[node];
        *reinterpret_cast<float2*>(g_t + (size_t)node * 36 + lane * 2) =
            make_float2(a0 * di, a1 * di);
    }
}

// ============================================================================
// f32x2 GEMM core: 16 rows per block (8 packed row-pairs), FOUT threads.
// hs2[k][r] transposed staging, pad to 18 for LDS.64 alignment.
// ============================================================================
template<int FIN, int FOUT, int KCHUNK>
__device__ __forceinline__ void gemm_core(const float* __restrict__ in,
                                          const float* __restrict__ W,
                                          int row0, int tid,
                                          unsigned long long (&acc2)[8],
                                          float (*Ws)[FOUT],
                                          float (*hs2)[18])
{
    constexpr int ROWS = 16;
#pragma unroll
    for (int rp = 0; rp < 8; rp++) acc2[rp] = 0ull;

    for (int kc = 0; kc < FIN; kc += KCHUNK) {
#pragma unroll
        for (int i = tid; i < KCHUNK * FOUT; i += FOUT)
            Ws[i / FOUT][tid] = W[(kc + i / FOUT) * FOUT + tid];
        constexpr int C4 = KCHUNK / 4;
        for (int i = tid; i < ROWS * C4; i += FOUT) {
            int r  = i / C4;
            int c4 = i % C4;
            float4 v = *reinterpret_cast<const float4*>(
                &in[(size_t)(row0 + r) * FIN + kc + c4 * 4]);
            hs2[c4 * 4 + 0][r] = v.x;
            hs2[c4 * 4 + 1][r] = v.y;
            hs2[c4 * 4 + 2][r] = v.z;
            hs2[c4 * 4 + 3][r] = v.w;
        }
        __syncthreads();

#pragma unroll
        for (int k = 0; k < KCHUNK; k++) {
            unsigned long long w2 = pack2(Ws[k][tid]);
            const unsigned long long* hp =
                reinterpret_cast<const unsigned long long*>(&hs2[k][0]);
#pragma unroll
            for (int rp = 0; rp < 8; rp++)
                fma2(acc2[rp], hp[rp], w2);
        }
        __syncthreads();
    }
}

// ---- GEMM with BN+ReLU epilogue (layer 0) ---------------------------------
template<int FIN, int FOUT, int KCHUNK>
__global__ void gemm_bn_kernel(const float* __restrict__ in,
                               const float* __restrict__ W,
                               const float* __restrict__ bias,
                               const float* __restrict__ bn_g,
                               const float* __restrict__ bn_b,
                               const float* __restrict__ bn_m,
                               const float* __restrict__ bn_v,
                               float* __restrict__ out)
{
    __shared__ float Ws[KCHUNK][FOUT];
    __shared__ float hs2[KCHUNK][18];
    const int row0 = blockIdx.x * 16;
    const int tid  = threadIdx.x;

    unsigned long long acc2[8];
    gemm_core<FIN, FOUT, KCHUNK>(in, W, row0, tid, acc2, Ws, hs2);

    float sc  = bn_g[tid] * rsqrtf(bn_v[tid] + BN_EPS);
    float shb = sc * (bias[tid] - bn_m[tid]) + bn_b[tid];
#pragma unroll
    for (int rp = 0; rp < 8; rp++) {
        float2 p = unpack2(acc2[rp]);
        out[(size_t)(row0 + 2 * rp + 0) * FOUT + tid] = fmaxf(fmaf(p.x, sc, shb), 0.0f);
        out[(size_t)(row0 + 2 * rp + 1) * FOUT + tid] = fmaxf(fmaf(p.y, sc, shb), 0.0f);
    }
}

// ---- GEMM with dinv-scale fp16 epilogue (layers 1,2) ----------------------
template<int FIN, int FOUT, int KCHUNK>
__global__ void gemm_h16_kernel(const float* __restrict__ in,
                                const float* __restrict__ W,
                                __half* __restrict__ xw)
{
    __shared__ float Ws[KCHUNK][FOUT];
    __shared__ float hs2[KCHUNK][18];
    const int row0 = blockIdx.x * 16;
    const int tid  = threadIdx.x;

    unsigned long long acc2[8];
    gemm_core<FIN, FOUT, KCHUNK>(in, W, row0, tid, acc2, Ws, hs2);

#pragma unroll
    for (int rp = 0; rp < 8; rp++) {
        float2 p = unpack2(acc2[rp]);
        int r0 = row0 + 2 * rp;
        xw[(size_t)(r0 + 0) * FOUT + tid] = __float2half_rn(p.x * g_dinv[r0 + 0]);
        xw[(size_t)(r0 + 1) * FOUT + tid] = __float2half_rn(p.y * g_dinv[r0 + 1]);
    }
}

// ---- fused CSR aggregation + dinv scale + BN + ReLU (+ pool) --------------
template<int FOUT, bool POOL>
__global__ void agg_kernel(const __half* __restrict__ xw,
                           const float* __restrict__ bias,
                           const float* __restrict__ bn_g,
                           const float* __restrict__ bn_b,
                           const float* __restrict__ bn_m,
                           const float* __restrict__ bn_v,
                           float* __restrict__ out,
                           const int* __restrict__ batch)
{
    constexpr int VEC = FOUT / 32;        // 4 (FOUT=128) or 2 (FOUT=64)
    __shared__ float s_sc [FOUT];
    __shared__ float s_shb[FOUT];

    const int tid  = threadIdx.x;
    const int lane = tid & 31;
    const int wid  = tid >> 5;

    if (tid < FOUT) {
        float sc = bn_g[tid] * rsqrtf(bn_v[tid] + BN_EPS);
        s_sc [tid] = sc;
        s_shb[tid] = sc * (bias[tid] - bn_m[tid]) + bn_b[tid];
    }
    __syncthreads();

    const int node = blockIdx.x * 8 + wid;
    if (node >= N_NODES) return;

    const int beg = g_off[node];
    const int end = g_off[node + 1];

    float acc[VEC];
#pragma unroll
    for (int k = 0; k < VEC; k++) acc[k] = 0.0f;

    auto gather = [&](int s) {
        if constexpr (VEC == 4) {
            uint2 raw = *reinterpret_cast<const uint2*>(xw + (size_t)s * FOUT + lane * 4);
            float2 f0 = __half22float2(*reinterpret_cast<__half2*>(&raw.x));
            float2 f1 = __half22float2(*reinterpret_cast<__half2*>(&raw.y));
            acc[0] += f0.x; acc[1] += f0.y;
            acc[2] += f1.x; acc[3] += f1.y;
        } else {
            __half2 raw = *reinterpret_cast<const __half2*>(xw + (size_t)s * FOUT + lane * 2);
            float2 f0 = __half22float2(raw);
            acc[0] += f0.x; acc[1] += f0.y;
        }
    };

    int b = beg;
    const int nfull = (end - beg) & ~31;
    for (; b < beg + nfull; b += 32) {
        int pk = g_csr[b + lane];
#pragma unroll 8
        for (int j = 0; j < 32; j++) {
            int s = __shfl_sync(0xffffffffu, pk, j);
            gather(s);
        }
    }
    if (b < end) {
        int e = b + lane;
        int ssrc = (e < end) ? g_csr[e] : 0;
        int cnt = end - b;
        for (int j = 0; j < cnt; j++) {
            int s = __shfl_sync(0xffffffffu, ssrc, j);
            gather(s);
        }
    }
    gather(node);   // self loop

    const float di = g_dinv[node];
    float y[VEC];
#pragma unroll
    for (int k = 0; k < VEC; k++) {
        int col = lane * VEC + k;
        y[k] = fmaxf(fmaf(acc[k] * di, s_sc[col], s_shb[col]), 0.0f);
    }

    if constexpr (POOL) {
        int g = batch[node];
#pragma unroll
        for (int k = 0; k < VEC; k++)
            red_add_f32(&g_sums[(size_t)g * 64 + lane * VEC + k], y[k]);
        if (lane == 0) red_add_f32(&g_cnt[g], 1.0f);
    } else {
        if constexpr (VEC == 4) {
            reinterpret_cast<float4*>(out)[(size_t)node * 32 + lane] =
                make_float4(y[0], y[1], y[2], y[3]);
        } else {
            reinterpret_cast<float2*>(out)[(size_t)node * 32 + lane] =
                make_float2(y[0], y[1]);
        }
    }
}

// ---- MLP head: one block (128 thr) per graph ------------------------------
__global__ void head_kernel(const float* __restrict__ fw0, const float* __restrict__ fb0,
                            const float* __restrict__ fw1, const float* __restrict__ fb1,
                            const float* __restrict__ ow,  const float* __restrict__ ob,
                            float* __restrict__ out)
{
    __shared__ float pooled[64], h0[128], h1[64];
    const int g = blockIdx.x;
    const int t = threadIdx.x;

    float inv = 1.0f / fmaxf(g_cnt[g], 1.0f);
    if (t < 64) pooled[t] = g_sums[(size_t)g * 64 + t] * inv;
    __syncthreads();

    float a = fb0[t];
#pragma unroll
    for (int k = 0; k < 64; k++) a = fmaf(pooled[k], fw0[k * 128 + t], a);
    h0[t] = fmaxf(a, 0.0f);
    __syncthreads();

    if (t < 64) {
        float b = fb1[t];
#pragma unroll
        for (int k = 0; k < 128; k++) b = fmaf(h0[k], fw1[k * 64 + t], b);
        h1[t] = fmaxf(b, 0.0f);
    }
    __syncthreads();

    if (t < 2) {
        float o = ob[t];
#pragma unroll
        for (int k = 0; k < 64; k++) o = fmaf(h1[k], ow[k * 2 + t], o);
        out[(size_t)g * 2 + t] = o;
    }
}

// ---------------------------------------------------------------------------
extern "C" void kernel_launch(void* const* d_in, const int* in_sizes, int n_in,
                              void* d_out, int out_size)
{
    const float* x          = (const float*)d_in[0];
    const int*   edge_index = (const int*)  d_in[1];
    const int*   batch      = (const int*)  d_in[2];

    int p = 3;
    if (in_sizes[3] == 1) p = 4;   // num_graphs scalar, if materialized

    const float* W [3]; const float* B [3];
    const float* Gm[3]; const float* Be[3];
    const float* Mn[3]; const float* Vr[3];
    for (int l = 0; l < 3; l++) {
        W [l] = (const float*)d_in[p + 6 * l + 0];
        B [l] = (const float*)d_in[p + 6 * l + 1];
        Gm[l] = (const float*)d_in[p + 6 * l + 2];
        Be[l] = (const float*)d_in[p + 6 * l + 3];
        Mn[l] = (const float*)d_in[p + 6 * l + 4];
        Vr[l] = (const float*)d_in[p + 6 * l + 5];
    }
    const float* fw0 = (const float*)d_in[p + 18];
    const float* fb0 = (const float*)d_in[p + 19];
    const float* fw1 = (const float*)d_in[p + 20];
    const float* fb1 = (const float*)d_in[p + 21];
    const float* ow  = (const float*)d_in[p + 22];
    const float* ob  = (const float*)d_in[p + 23];
    float* out = (float*)d_out;

    const int* src = edge_index;
    const int* dst = edge_index + N_EDGES;

    __half* xw;
    float*  bufB;
    float*  tbuf;
    void *ecntp, *sumsp, *cntp;
    cudaGetSymbolAddress((void**)&xw,   g_xw);
    cudaGetSymbolAddress((void**)&bufB, g_bufB);
    cudaGetSymbolAddress((void**)&tbuf, g_t);
    cudaGetSymbolAddress(&ecntp, g_ecnt);
    cudaGetSymbolAddress(&sumsp, g_sums);
    cudaGetSymbolAddress(&cntp,  g_cnt);

    // CSR build
    cudaMemsetAsync(ecntp, 0, N_NODES * sizeof(int));
    deg_count_kernel<<<2048, 256>>>(dst);
    scan_blocks_kernel<<<NB_SCAN, 1024>>>();
    scan_bsum_kernel<<<1, 128>>>();
    dinv_kernel<<<(N_NODES + 255) / 256, 256>>>();
    fill_kernel<<<2048, 256>>>(src, dst);

    const int GEMM_BLOCKS = N_NODES / 16;            // 6250 exact
    const int AGG_BLOCKS  = (N_NODES + 7) / 8;       // 12500

    // layer 0: xs = x*dinv -> t = Â-gather -> h = relu(bn(t@W0 + b))
    x2h_kernel<<<(N_NODES * 36 + 255) / 256, 256>>>(x);
    agg0_kernel<<<AGG_BLOCKS, 256>>>();
    gemm_bn_kernel<36, 128, 36><<<GEMM_BLOCKS, 128>>>(
        tbuf, W[0], B[0], Gm[0], Be[0], Mn[0], Vr[0], bufB);

    // layer 1
    gemm_h16_kernel<128, 128, 64><<<GEMM_BLOCKS, 128>>>(bufB, W[1], xw);
    agg_kernel<128, false><<<AGG_BLOCKS, 256>>>(xw, B[1], Gm[1], Be[1], Mn[1], Vr[1], bufB, nullptr);

    // layer 2 + pool
    gemm_h16_kernel<128, 64, 64><<<GEMM_BLOCKS, 64>>>(bufB, W[2], xw);
    cudaMemsetAsync(sumsp, 0, N_GRAPHS * 64 * sizeof(float));
    cudaMemsetAsync(cntp,  0, N_GRAPHS * sizeof(float));
    agg_kernel<64, true><<<AGG_BLOCKS, 256>>>(xw, B[2], Gm[2], Be[2], Mn[2], Vr[2], nullptr, batch);

    // head
    head_kernel<<<N_GRAPHS, 128>>>(fw0, fb0, fw1, fb1, ow, ob, out);
}

// round 8
// speedup vs baseline: 2.3967x; 2.3967x over previous
#include <cuda_runtime.h>
#include <cuda_fp16.h>
#include <math.h>
#include <stdint.h>

// ---------------------------------------------------------------------------
// MolecularGNN: 3x GCNConv(+BN+ReLU) -> global mean pool -> MLP head
// CSR src-only gather + fp16 features + mma.sync (HMMA) GEMMs for layers 1,2.
// ---------------------------------------------------------------------------

#define N_NODES  100000
#define N_EDGES  3200000
#define N_GRAPHS 4096
#define BN_EPS   1e-5f
#define NB_SCAN  98          // ceil(100000/1024)

// ---- scratch (device globals; allocation-free rule) -----------------------
__device__ __align__(256) int    g_ecnt  [N_NODES];
__device__ __align__(256) int    g_off   [N_NODES + 1];
__device__ __align__(256) int    g_cursor[N_NODES];
__device__ __align__(256) int    g_bsum  [NB_SCAN];
__device__ __align__(256) int    g_boff  [NB_SCAN];
__device__ __align__(256) float  g_dinv  [N_NODES];
__device__ __align__(256) int    g_csr   [N_EDGES];        // src only
__device__ __align__(256) __half g_xs    [N_NODES * 36];   // x * dinv (fp16)
__device__ __align__(256) float  g_t     [N_NODES * 36];   // aggregated x (fp32)
__device__ __align__(256) __half g_xw    [N_NODES * 128];  // (h@W)*dinv (fp16)
__device__ __align__(256) __half g_h16   [N_NODES * 128];  // h (fp16)
__device__ __align__(256) __half g_w16a  [128 * 128];      // W1 fp16
__device__ __align__(256) __half g_w16b  [128 * 64];       // W2 fp16
__device__ __align__(256) float  g_sums  [N_GRAPHS * 64];
__device__ __align__(256) float  g_cnt   [N_GRAPHS];

__device__ __forceinline__ void red_add_f32(float* p, float v) {
    asm volatile("red.global.add.f32 [%0], %1;" :: "l"(p), "f"(v) : "memory");
}

// ---- mma helpers ----------------------------------------------------------
__device__ __forceinline__ void ldsm4(uint32_t* r, const void* p) {
    uint32_t addr = (uint32_t)__cvta_generic_to_shared(p);
    asm volatile("ldmatrix.sync.aligned.m8n8.x4.shared.b16 {%0,%1,%2,%3}, [%4];"
        : "=r"(r[0]), "=r"(r[1]), "=r"(r[2]), "=r"(r[3]) : "r"(addr));
}
__device__ __forceinline__ void ldsm4t(uint32_t* r, const void* p) {
    uint32_t addr = (uint32_t)__cvta_generic_to_shared(p);
    asm volatile("ldmatrix.sync.aligned.m8n8.x4.trans.shared.b16 {%0,%1,%2,%3}, [%4];"
        : "=r"(r[0]), "=r"(r[1]), "=r"(r[2]), "=r"(r[3]) : "r"(addr));
}
__device__ __forceinline__ void mma16816(float* c, const uint32_t* a,
                                         uint32_t b0, uint32_t b1) {
    asm volatile("mma.sync.aligned.m16n8k16.row.col.f32.f16.f16.f32 "
        "{%0,%1,%2,%3}, {%4,%5,%6,%7}, {%8,%9}, {%0,%1,%2,%3};"
        : "+f"(c[0]), "+f"(c[1]), "+f"(c[2]), "+f"(c[3])
        : "r"(a[0]), "r"(a[1]), "r"(a[2]), "r"(a[3]), "r"(b0), "r"(b1));
}

// ---- degree count ---------------------------------------------------------
__global__ void deg_count_kernel(const int* __restrict__ dst) {
    int stride = gridDim.x * blockDim.x;
    for (int e = blockIdx.x * blockDim.x + threadIdx.x; e < N_EDGES; e += stride)
        atomicAdd(&g_ecnt[dst[e]], 1);
}

// ---- multi-block exclusive scan over g_ecnt -------------------------------
__global__ void scan_blocks_kernel() {   // NB_SCAN blocks x 1024
    __shared__ int wsum[32];
    const int t    = threadIdx.x;
    const int lane = t & 31;
    const int w    = t >> 5;
    const int i    = blockIdx.x * 1024 + t;
    int v = (i < N_NODES) ? g_ecnt[i] : 0;
    int s = v;
#pragma unroll
    for (int o = 1; o < 32; o <<= 1) {
        int u = __shfl_up_sync(0xffffffffu, s, o);
        if (lane >= o) s += u;
    }
    if (lane == 31) wsum[w] = s;
    __syncthreads();
    if (w == 0) {
        int ws = wsum[lane];
        int tt = ws;
#pragma unroll
        for (int o = 1; o < 32; o <<= 1) {
            int u = __shfl_up_sync(0xffffffffu, tt, o);
            if (lane >= o) tt += u;
        }
        wsum[lane] = tt - ws;   // exclusive warp offset
    }
    __syncthreads();
    int excl = s - v + wsum[w];
    if (i < N_NODES) g_off[i] = excl;
    if (t == 1023) g_bsum[blockIdx.x] = excl + v;   // block total
}

__global__ void scan_bsum_kernel() {     // 1 block x 128
    __shared__ int sh[128];
    const int t = threadIdx.x;
    int v = (t < NB_SCAN) ? g_bsum[t] : 0;
    sh[t] = v;
    __syncthreads();
    for (int o = 1; o < 128; o <<= 1) {
        int u = (t >= o) ? sh[t - o] : 0;
        __syncthreads();
        sh[t] += u;
        __syncthreads();
    }
    if (t < NB_SCAN) g_boff[t] = sh[t] - v;
    if (t == 127)    g_off[N_NODES] = sh[127];
}

// ---- finalize offsets + dinv + cursor -------------------------------------
__global__ void dinv_kernel() {
    int i = blockIdx.x * blockDim.x + threadIdx.x;
    if (i < N_NODES) {
        int off = g_off[i] + g_boff[i >> 10];
        g_off[i]    = off;
        g_cursor[i] = off;
        g_dinv[i]   = rsqrtf((float)g_ecnt[i] + 1.0f);
    }
}

// ---- CSR fill (src only) --------------------------------------------------
__global__ void fill_kernel(const int* __restrict__ src, const int* __restrict__ dst) {
    int stride = gridDim.x * blockDim.x;
    for (int e = blockIdx.x * blockDim.x + threadIdx.x; e < N_EDGES; e += stride) {
        int d = dst[e];
        int pos = atomicAdd(&g_cursor[d], 1);
        g_csr[pos] = src[e];
    }
}

// ---- x * dinv -> fp16 ; weight fp32 -> fp16 -------------------------------
__global__ void x2h_kernel(const float* __restrict__ x) {
    int i = blockIdx.x * blockDim.x + threadIdx.x;   // over N_NODES*36
    if (i < N_NODES * 36) {
        int n = i / 36;
        g_xs[i] = __float2half_rn(x[i] * g_dinv[n]);
    }
}

__global__ void w2h_kernel(const float* __restrict__ w1, const float* __restrict__ w2) {
    int i = blockIdx.x * blockDim.x + threadIdx.x;
    if (i < 128 * 128) g_w16a[i] = __float2half_rn(w1[i]);
    if (i < 128 * 64)  g_w16b[i] = __float2half_rn(w2[i]);
}

// ---- layer-0 aggregation over 36-wide fp16 rows ---------------------------
__global__ void agg0_kernel() {
    const int tid  = threadIdx.x;
    const int lane = tid & 31;
    const int wid  = tid >> 5;
    const int node = blockIdx.x * 8 + wid;
    if (node >= N_NODES) return;

    const int beg = g_off[node];
    const int end = g_off[node + 1];

    float a0 = 0.0f, a1 = 0.0f;
    const bool act = (lane < 18);

    auto gather = [&](int s) {
        if (act) {
            __half2 v = *reinterpret_cast<const __half2*>(g_xs + (size_t)s * 36 + lane * 2);
            float2 f = __half22float2(v);
            a0 += f.x; a1 += f.y;
        }
    };

    int b = beg;
    const int nfull = (end - beg) & ~31;
    for (; b < beg + nfull; b += 32) {
        int pk = g_csr[b + lane];
#pragma unroll 8
        for (int j = 0; j < 32; j++) {
            int s = __shfl_sync(0xffffffffu, pk, j);
            gather(s);
        }
    }
    if (b < end) {
        int e = b + lane;
        int ssrc = (e < end) ? g_csr[e] : 0;
        int cnt = end - b;
        for (int j = 0; j < cnt; j++) {
            int s = __shfl_sync(0xffffffffu, ssrc, j);
            gather(s);
        }
    }
    gather(node);   // self loop

    if (act) {
        float di = g_dinv[node];
        *reinterpret_cast<float2*>(g_t + (size_t)node * 36 + lane * 2) =
            make_float2(a0 * di, a1 * di);
    }
}

// ---- layer-0 GEMM (scalar, R5 core) with BN+ReLU epilogue -> fp16 h -------
template<int FIN, int FOUT, int KCHUNK>
__global__ void gemm_bn_kernel(const float* __restrict__ in,
                               const float* __restrict__ W,
                               const float* __restrict__ bias,
                               const float* __restrict__ bn_g,
                               const float* __restrict__ bn_b,
                               const float* __restrict__ bn_m,
                               const float* __restrict__ bn_v,
                               __half* __restrict__ out)
{
    constexpr int ROWS = 16;
    __shared__ float Ws[KCHUNK][FOUT];
    __shared__ float hs[ROWS][KCHUNK];

    const int row0 = blockIdx.x * ROWS;
    const int tid  = threadIdx.x;

    float acc[ROWS];
#pragma unroll
    for (int r = 0; r < ROWS; r++) acc[r] = 0.0f;

    for (int kc = 0; kc < FIN; kc += KCHUNK) {
#pragma unroll
        for (int i = tid; i < KCHUNK * FOUT; i += FOUT)
            Ws[i / FOUT][tid] = W[(kc + i / FOUT) * FOUT + tid];
        constexpr int HV = ROWS * KCHUNK / 4;
        for (int i = tid; i < HV; i += FOUT) {
            int r  = i / (KCHUNK / 4);
            int c4 = i % (KCHUNK / 4);
            float4 v = *reinterpret_cast<const float4*>(
                &in[(size_t)(row0 + r) * FIN + kc + c4 * 4]);
            *reinterpret_cast<float4*>(&hs[r][c4 * 4]) = v;
        }
        __syncthreads();

#pragma unroll
        for (int k = 0; k < KCHUNK; k += 4) {
            float w0 = Ws[k + 0][tid];
            float w1 = Ws[k + 1][tid];
            float w2 = Ws[k + 2][tid];
            float w3 = Ws[k + 3][tid];
#pragma unroll
            for (int r = 0; r < ROWS; r++) {
                float4 h4 = *reinterpret_cast<const float4*>(&hs[r][k]);
                float a = acc[r];
                a = fmaf(h4.x, w0, a);
                a = fmaf(h4.y, w1, a);
                a = fmaf(h4.z, w2, a);
                a = fmaf(h4.w, w3, a);
                acc[r] = a;
            }
        }
        __syncthreads();
    }

    float sc  = bn_g[tid] * rsqrtf(bn_v[tid] + BN_EPS);
    float shb = sc * (bias[tid] - bn_m[tid]) + bn_b[tid];
#pragma unroll
    for (int r = 0; r < ROWS; r++)
        out[(size_t)(row0 + r) * FOUT + tid] =
            __float2half_rn(fmaxf(fmaf(acc[r], sc, shb), 0.0f));
}

// ---- tensor-core GEMM (layers 1,2): C = (A[N,128] @ B[128,FOUT]) * dinv ----
// 128 threads = 4 warps; block tile 64 rows; fp16 in, fp32 accum, fp16 out.
template<int FOUT>
__global__ __launch_bounds__(128) void mma_gemm_kernel(const __half* __restrict__ A,
                                                       const __half* __restrict__ Bw,
                                                       __half* __restrict__ Cout)
{
    constexpr int FIN = 128;
    constexpr int NF  = FOUT / 8;      // n-fragments
    __shared__ __half As[64][FIN + 8];
    __shared__ __half Bs[64][FOUT + 8];

    const int tid  = threadIdx.x;
    const int lane = tid & 31;
    const int warp = tid >> 5;
    const int row0 = blockIdx.x * 64;

    // stage A tile (64 x 128), zero-fill OOB rows
    {
        constexpr int RV = FIN / 8;    // 16 uint4 per row
        for (int i = tid; i < 64 * RV; i += 128) {
            int r = i / RV, c = i % RV;
            uint4 v = make_uint4(0u, 0u, 0u, 0u);
            if (row0 + r < N_NODES)
                v = *reinterpret_cast<const uint4*>(A + (size_t)(row0 + r) * FIN + c * 8);
            *reinterpret_cast<uint4*>(&As[r][c * 8]) = v;
        }
    }

    float acc[NF][4];
#pragma unroll
    for (int nf = 0; nf < NF; nf++)
#pragma unroll
        for (int j = 0; j < 4; j++) acc[nf][j] = 0.0f;

    const int wrow = warp * 16;
    const int arow = wrow + (lane & 15);
    const int acol8 = (lane >> 4) * 8;

#pragma unroll
    for (int kc = 0; kc < 2; kc++) {
        __syncthreads();   // A staged (kc=0) / all warps done reading Bs (kc=1)
        {
            constexpr int BV = FOUT / 8;
            for (int i = tid; i < 64 * BV; i += 128) {
                int r = i / BV, c = i % BV;
                *reinterpret_cast<uint4*>(&Bs[r][c * 8]) =
                    *reinterpret_cast<const uint4*>(Bw + (size_t)(kc * 64 + r) * FOUT + c * 8);
            }
        }
        __syncthreads();

#pragma unroll
        for (int kk = 0; kk < 4; kk++) {
            uint32_t ra[4];
            ldsm4(ra, &As[arow][kc * 64 + kk * 16 + acol8]);
            const int brow = kk * 16 + (lane & 15);
#pragma unroll
            for (int np = 0; np < NF / 2; np++) {
                uint32_t rb[4];
                ldsm4t(rb, &Bs[brow][np * 16 + acol8]);
                mma16816(acc[2 * np + 0], ra, rb[0], rb[1]);
                mma16816(acc[2 * np + 1], ra, rb[2], rb[3]);
            }
        }
    }

    // epilogue: scale by dinv[row], fp16 store
    const int r0 = row0 + wrow + (lane >> 2);
    const int r1 = r0 + 8;
    const float d0 = (r0 < N_NODES) ? g_dinv[r0] : 0.0f;
    const float d1 = (r1 < N_NODES) ? g_dinv[r1] : 0.0f;
#pragma unroll
    for (int nf = 0; nf < NF; nf++) {
        int col = nf * 8 + (lane & 3) * 2;
        if (r0 < N_NODES)
            *reinterpret_cast<__half2*>(Cout + (size_t)r0 * FOUT + col) =
                __floats2half2_rn(acc[nf][0] * d0, acc[nf][1] * d0);
        if (r1 < N_NODES)
            *reinterpret_cast<__half2*>(Cout + (size_t)r1 * FOUT + col) =
                __floats2half2_rn(acc[nf][2] * d1, acc[nf][3] * d1);
    }
}

// ---- fused CSR aggregation + dinv scale + BN + ReLU (+ pool) --------------
// One warp per dst node; non-pool variant writes fp16 h.
template<int FOUT, bool POOL>
__global__ void agg_kernel(const __half* __restrict__ xw,
                           const float* __restrict__ bias,
                           const float* __restrict__ bn_g,
                           const float* __restrict__ bn_b,
                           const float* __restrict__ bn_m,
                           const float* __restrict__ bn_v,
                           __half* __restrict__ out,
                           const int* __restrict__ batch)
{
    constexpr int VEC = FOUT / 32;        // 4 (FOUT=128) or 2 (FOUT=64)
    __shared__ float s_sc [FOUT];
    __shared__ float s_shb[FOUT];

    const int tid  = threadIdx.x;
    const int lane = tid & 31;
    const int wid  = tid >> 5;

    if (tid < FOUT) {
        float sc = bn_g[tid] * rsqrtf(bn_v[tid] + BN_EPS);
        s_sc [tid] = sc;
        s_shb[tid] = sc * (bias[tid] - bn_m[tid]) + bn_b[tid];
    }
    __syncthreads();

    const int node = blockIdx.x * 8 + wid;
    if (node >= N_NODES) return;

    const int beg = g_off[node];
    const int end = g_off[node + 1];

    float acc[VEC];
#pragma unroll
    for (int k = 0; k < VEC; k++) acc[k] = 0.0f;

    auto gather = [&](int s) {
        if constexpr (VEC == 4) {
            uint2 raw = *reinterpret_cast<const uint2*>(xw + (size_t)s * FOUT + lane * 4);
            float2 f0 = __half22float2(*reinterpret_cast<__half2*>(&raw.x));
            float2 f1 = __half22float2(*reinterpret_cast<__half2*>(&raw.y));
            acc[0] += f0.x; acc[1] += f0.y;
            acc[2] += f1.x; acc[3] += f1.y;
        } else {
            __half2 raw = *reinterpret_cast<const __half2*>(xw + (size_t)s * FOUT + lane * 2);
            float2 f0 = __half22float2(raw);
            acc[0] += f0.x; acc[1] += f0.y;
        }
    };

    int b = beg;
    const int nfull = (end - beg) & ~31;
    for (; b < beg + nfull; b += 32) {
        int pk = g_csr[b + lane];
#pragma unroll 8
        for (int j = 0; j < 32; j++) {
            int s = __shfl_sync(0xffffffffu, pk, j);
            gather(s);
        }
    }
    if (b < end) {
        int e = b + lane;
        int ssrc = (e < end) ? g_csr[e] : 0;
        int cnt = end - b;
        for (int j = 0; j < cnt; j++) {
            int s = __shfl_sync(0xffffffffu, ssrc, j);
            gather(s);
        }
    }
    gather(node);   // self loop

    const float di = g_dinv[node];
    float y[VEC];
#pragma unroll
    for (int k = 0; k < VEC; k++) {
        int col = lane * VEC + k;
        y[k] = fmaxf(fmaf(acc[k] * di, s_sc[col], s_shb[col]), 0.0f);
    }

    if constexpr (POOL) {
        int g = batch[node];
#pragma unroll
        for (int k = 0; k < VEC; k++)
            red_add_f32(&g_sums[(size_t)g * 64 + lane * VEC + k], y[k]);
        if (lane == 0) red_add_f32(&g_cnt[g], 1.0f);
    } else {
        if constexpr (VEC == 4) {
            __half2 p0 = __floats2half2_rn(y[0], y[1]);
            __half2 p1 = __floats2half2_rn(y[2], y[3]);
            uint2 u;
            u.x = *reinterpret_cast<uint32_t*>(&p0);
            u.y = *reinterpret_cast<uint32_t*>(&p1);
            *reinterpret_cast<uint2*>(out + (size_t)node * FOUT + lane * 4) = u;
        } else {
            __half2 p0 = __floats2half2_rn(y[0], y[1]);
            *reinterpret_cast<__half2*>(out + (size_t)node * FOUT + lane * 2) = p0;
        }
    }
}

// ---- MLP head: one block (128 thr) per graph ------------------------------
__global__ void head_kernel(const float* __restrict__ fw0, const float* __restrict__ fb0,
                            const float* __restrict__ fw1, const float* __restrict__ fb1,
                            const float* __restrict__ ow,  const float* __restrict__ ob,
                            float* __restrict__ out)
{
    __shared__ float pooled[64], h0[128], h1[64];
    const int g = blockIdx.x;
    const int t = threadIdx.x;

    float inv = 1.0f / fmaxf(g_cnt[g], 1.0f);
    if (t < 64) pooled[t] = g_sums[(size_t)g * 64 + t] * inv;
    __syncthreads();

    float a = fb0[t];
#pragma unroll
    for (int k = 0; k < 64; k++) a = fmaf(pooled[k], fw0[k * 128 + t], a);
    h0[t] = fmaxf(a, 0.0f);
    __syncthreads();

    if (t < 64) {
        float b = fb1[t];
#pragma unroll
        for (int k = 0; k < 128; k++) b = fmaf(h0[k], fw1[k * 64 + t], b);
        h1[t] = fmaxf(b, 0.0f);
    }
    __syncthreads();

    if (t < 2) {
        float o = ob[t];
#pragma unroll
        for (int k = 0; k < 64; k++) o = fmaf(h1[k], ow[k * 2 + t], o);
        out[(size_t)g * 2 + t] = o;
    }
}

// ---------------------------------------------------------------------------
extern "C" void kernel_launch(void* const* d_in, const int* in_sizes, int n_in,
                              void* d_out, int out_size)
{
    const float* x          = (const float*)d_in[0];
    const int*   edge_index = (const int*)  d_in[1];
    const int*   batch      = (const int*)  d_in[2];

    int p = 3;
    if (in_sizes[3] == 1) p = 4;   // num_graphs scalar, if materialized

    const float* W [3]; const float* B [3];
    const float* Gm[3]; const float* Be[3];
    const float* Mn[3]; const float* Vr[3];
    for (int l = 0; l < 3; l++) {
        W [l] = (const float*)d_in[p + 6 * l + 0];
        B [l] = (const float*)d_in[p + 6 * l + 1];
        Gm[l] = (const float*)d_in[p + 6 * l + 2];
        Be[l] = (const float*)d_in[p + 6 * l + 3];
        Mn[l] = (const float*)d_in[p + 6 * l + 4];
        Vr[l] = (const float*)d_in[p + 6 * l + 5];
    }
    const float* fw0 = (const float*)d_in[p + 18];
    const float* fb0 = (const float*)d_in[p + 19];
    const float* fw1 = (const float*)d_in[p + 20];
    const float* fb1 = (const float*)d_in[p + 21];
    const float* ow  = (const float*)d_in[p + 22];
    const float* ob  = (const float*)d_in[p + 23];
    float* out = (float*)d_out;

    const int* src = edge_index;
    const int* dst = edge_index + N_EDGES;

    __half *xw, *h16, *w16a, *w16b;
    float  *tbuf;
    void *ecntp, *sumsp, *cntp;
    cudaGetSymbolAddress((void**)&xw,   g_xw);
    cudaGetSymbolAddress((void**)&h16,  g_h16);
    cudaGetSymbolAddress((void**)&w16a, g_w16a);
    cudaGetSymbolAddress((void**)&w16b, g_w16b);
    cudaGetSymbolAddress((void**)&tbuf, g_t);
    cudaGetSymbolAddress(&ecntp, g_ecnt);
    cudaGetSymbolAddress(&sumsp, g_sums);
    cudaGetSymbolAddress(&cntp,  g_cnt);

    // CSR build
    cudaMemsetAsync(ecntp, 0, N_NODES * sizeof(int));
    deg_count_kernel<<<2048, 256>>>(dst);
    scan_blocks_kernel<<<NB_SCAN, 1024>>>();
    scan_bsum_kernel<<<1, 128>>>();
    dinv_kernel<<<(N_NODES + 255) / 256, 256>>>();
    fill_kernel<<<2048, 256>>>(src, dst);

    const int GEMM_BLOCKS = N_NODES / 16;            // 6250 exact
    const int AGG_BLOCKS  = (N_NODES + 7) / 8;       // 12500
    const int MMA_BLOCKS  = (N_NODES + 63) / 64;     // 1563

    // weight conversion (tiny)
    w2h_kernel<<<(128 * 128 + 255) / 256, 256>>>(W[1], W[2]);

    // layer 0: xs = x*dinv -> t = Â-gather -> h16 = relu(bn(t@W0 + b))
    x2h_kernel<<<(N_NODES * 36 + 255) / 256, 256>>>(x);
    agg0_kernel<<<AGG_BLOCKS, 256>>>();
    gemm_bn_kernel<36, 128, 36><<<GEMM_BLOCKS, 128>>>(
        tbuf, W[0], B[0], Gm[0], Be[0], Mn[0], Vr[0], h16);

    // layer 1: xw = (h16 @ W1)*dinv  (tensor core) -> h16 = agg+BN+ReLU
    mma_gemm_kernel<128><<<MMA_BLOCKS, 128>>>(h16, w16a, xw);
    agg_kernel<128, false><<<AGG_BLOCKS, 256>>>(xw, B[1], Gm[1], Be[1], Mn[1], Vr[1], h16, nullptr);

    // layer 2: xw = (h16 @ W2)*dinv (tensor core) -> pool
    mma_gemm_kernel<64><<<MMA_BLOCKS, 128>>>(h16, w16b, xw);
    cudaMemsetAsync(sumsp, 0, N_GRAPHS * 64 * sizeof(float));
    cudaMemsetAsync(cntp,  0, N_GRAPHS * sizeof(float));
    agg_kernel<64, true><<<AGG_BLOCKS, 256>>>(xw, B[2], Gm[2], Be[2], Mn[2], Vr[2], nullptr, batch);

    // head
    head_kernel<<<N_GRAPHS, 128>>>(fw0, fb0, fw1, fb1, ow, ob, out);
}